// round 14
// baseline (speedup 1.0000x reference)
#include <cuda_runtime.h>
#include <cuda_fp16.h>
#include <cstdint>
#include <math.h>

// ---------------- configuration ----------------
#define TT_B   32
#define TT_N   2048
#define NCTA   128          // 16 colgroups x 8 K-splits (single wave)
#define TPB    512          // 16 warps = 8 mtiles x 2 khalves
#define KS_N   8
#define KSLICE 256          // K per CTA
#define MTILE  128          // j per CTA

// SMEM layout
#define SM_B      0                        // 2 limb tiles [256 k][64B], swizzled
#define BTILE     16384
#define SM_RED    (2 * BTILE)              // 32768 ; 8 mtiles x 16j x 160B
#define REDP      160
#define SM_PT     (SM_RED + 8 * 16 * REDP) // 53248 ; partial tile 32 x 528B
#define PTPITCH   132                      // floats per b-row (528B, bank-clean)
#define SM_BOUNCE (SM_PT + TT_B * PTPITCH * 4)   // 70144 ; 32 rows x 64B
#define SM_MBAR   (SM_BOUNCE + 2048)       // 72192 ; four mbars
#define SM_TOTAL  (SM_MBAR + 64)

// ---------------- device globals ----------------
// s limbs TRANSPOSED: [parity][limb][k(neuron)][b] fp16, 64B rows, chunk-swizzled
__device__ __align__(128) __half g_sT[2][2][TT_N][TT_B];
__device__ __align__(128) float g_part[2][NCTA][TT_B][MTILE]; // [par][cta][b][j]
__device__ unsigned g_sready[8];    // per s-slice publish counters (+16/step)
__device__ unsigned g_pready[16];   // per cg-row partial counters (+8/step)

__global__ void lif_init_kernel() {
    for (int i = 0; i < 8; ++i) g_sready[i] = 0u;
    for (int i = 0; i < 16; ++i) g_pready[i] = 0u;
}

// ---------------- helpers ----------------
__device__ __forceinline__ void mma_f16(float* d, const uint32_t* a,
                                        uint32_t b0, uint32_t b1) {
    asm volatile("mma.sync.aligned.m16n8k16.row.col.f32.f16.f16.f32 "
                 "{%0,%1,%2,%3}, {%4,%5,%6,%7}, {%8,%9}, {%0,%1,%2,%3};"
                 : "+f"(d[0]), "+f"(d[1]), "+f"(d[2]), "+f"(d[3])
                 : "r"(a[0]), "r"(a[1]), "r"(a[2]), "r"(a[3]),
                   "r"(b0), "r"(b1));
}
__device__ __forceinline__ void ldmT(uint32_t* r, uint32_t addr) {
    asm volatile("ldmatrix.sync.aligned.m8n8.x4.trans.shared.b16 {%0,%1,%2,%3}, [%4];"
                 : "=r"(r[0]), "=r"(r[1]), "=r"(r[2]), "=r"(r[3]) : "r"(addr));
}
__device__ __forceinline__ uint32_t smem_u32(const void* p) {
    uint32_t a;
    asm("{ .reg .u64 t; cvta.to.shared.u64 t, %1; cvt.u32.u64 %0, t; }" : "=r"(a) : "l"(p));
    return a;
}
__device__ __forceinline__ void mbar_init(uint32_t mbar, uint32_t cnt) {
    asm volatile("mbarrier.init.shared.b64 [%0], %1;" :: "r"(mbar), "r"(cnt) : "memory");
}
__device__ __forceinline__ void mbar_arrive_tx(uint32_t mbar, uint32_t bytes) {
    asm volatile("mbarrier.arrive.expect_tx.shared.b64 _, [%0], %1;"
                 :: "r"(mbar), "r"(bytes) : "memory");
}
__device__ __forceinline__ void mbar_wait(uint32_t mbar, uint32_t parity) {
    asm volatile("{\n\t.reg .pred P1;\n\tWL%=:\n\t"
                 "mbarrier.try_wait.parity.acquire.cta.shared::cta.b64 P1, [%0], %1, 0x989680;\n\t"
                 "@P1 bra.uni WD%=;\n\tbra.uni WL%=;\n\tWD%=:\n\t}"
                 :: "r"(mbar), "r"(parity) : "memory");
}
__device__ __forceinline__ void bulk_cp(uint32_t dst, const void* src,
                                        uint32_t bytes, uint32_t mbar) {
    asm volatile("cp.async.bulk.shared::cluster.global.mbarrier::complete_tx::bytes "
                 "[%0], [%1], %2, [%3];"
                 :: "r"(dst), "l"(src), "r"(bytes), "r"(mbar) : "memory");
}
__device__ __forceinline__ void rel_add(unsigned* p) {
    asm volatile("red.release.gpu.global.add.u32 [%0], %1;"
                 :: "l"(p), "r"(1u) : "memory");
}
__device__ __forceinline__ void acq_spin(unsigned* p, unsigned tgt) {
    unsigned vv;
    do {
        asm volatile("ld.acquire.gpu.global.u32 %0, [%1];"
                     : "=r"(vv) : "l"(p) : "memory");
    } while (vv < tgt);
}
// exact 2-way fp16 split: x = h + m + eps, |eps| <= 2^-22 |x|
__device__ __forceinline__ void split2(float x, uint16_t& h, uint16_t& m) {
    __half hh = __float2half_rn(x);
    float r = x - __half2float(hh);
    __half mm = __float2half_rn(r);
    h = __half_as_ushort(hh); m = __half_as_ushort(mm);
}

__global__ void __launch_bounds__(TPB, 1)
lif_kernel(const float* __restrict__ x_in, const float* __restrict__ v0,
           const float* __restrict__ s0,   const float* __restrict__ w,
           const float* __restrict__ E_Lp, const float* __restrict__ tau_mp,
           const float* __restrict__ tau_sp, const int* __restrict__ ntype,
           float* __restrict__ out, int T)
{
    extern __shared__ char smem[];
    const uint32_t smb = smem_u32(smem);
    // mbar[khalf][chunk] : chunk = kst quarter-pair (kst 0-3 / 4-7)
    const uint32_t mb00 = smb + SM_MBAR;
    const uint32_t mb01 = smb + SM_MBAR + 8;
    const uint32_t mb10 = smb + SM_MBAR + 16;
    const uint32_t mb11 = smb + SM_MBAR + 24;

    const int tid   = threadIdx.x;
    const int lane  = tid & 31;
    const int wid   = tid >> 5;
    const int g     = lane >> 2;
    const int tg    = lane & 3;
    const int cg    = blockIdx.x >> 3;
    const int ks    = blockIdx.x & 7;
    const int khalf = wid & 1;
    const int mt    = wid >> 1;

    const int jbase = cg * MTILE + mt * 16;
    const int kbase = ks * KSLICE + khalf * 128;

    if (tid == 0) {
        mbar_init(mb00, 1); mbar_init(mb01, 1);
        mbar_init(mb10, 1); mbar_init(mb11, 1);
    }

    // ---- one-time A build: Weff[k][j] = w[k][j]*nt[k], diag 0; fp16 2-limb ----
    auto weff = [&](int k, int j) -> float {
        if (k == j) return 0.f;
        return w[(size_t)k * TT_N + j] * (float)__ldg(&ntype[k]);
    };
    uint32_t a_h[8][4], a_m[8][4];
#pragma unroll
    for (int kst = 0; kst < 8; ++kst) {
        const int rows[2] = { g, g + 8 };
        const int kk0[2]  = { kst * 16 + 2 * tg, kst * 16 + 2 * tg + 8 };
#pragma unroll
        for (int q = 0; q < 4; ++q) {
            int j = jbase + rows[q & 1];
            int k = kbase + kk0[q >> 1];
            uint16_t h0, m0, h1, m1;
            split2(weff(k,     j), h0, m0);
            split2(weff(k + 1, j), h1, m1);
            a_h[kst][q] = (uint32_t)h0 | ((uint32_t)h1 << 16);
            a_m[kst][q] = (uint32_t)m0 | ((uint32_t)m1 << 16);
        }
    }

    // ---- dynamics ownership: tid = b*16 + m16 ----
    const int b   = tid >> 4;
    const int m16 = tid & 15;
    const int j0  = cg * MTILE + ks * 16;
    const int jg  = j0 + m16;
    float v = v0[b * TT_N + jg];
    float s = s0[b * TT_N + jg];
    const float eL    = E_Lp[jg];
    const float tm    = tau_mp[jg];
    const float tsv   = tau_sp[jg];
    const float nR    = (30.0f - eL) * 1.1f;
    const float dvmax = 30.0f - eL;

    // swizzled byte offset of (b) within the 64B k-row of jg
    const int co = (((b >> 3) ^ ((jg >> 1) & 3)) * 16) + ((b & 7) * 2);

    {   // publish initial s limbs (parity 0), direct swizzled stores
        uint16_t h, m; split2(s, h, m);
        *(uint16_t*)((char*)&g_sT[0][0][jg][0] + co) = h;
        *(uint16_t*)((char*)&g_sT[0][1][jg][0] + co) = m;
    }
    __syncthreads();
    if (tid == 0) rel_add(&g_sready[cg >> 1]);   // initial publish -> t=0 ready

    // ldmatrix lane address bases (R6-validated swizzle)
    const int r8  = lane & 7;
    const int sel = lane >> 3;
    const int swl = (r8 >> 1) & 3;
    const int klrow = khalf * 128 + (sel & 1) * 8 + r8;
    const uint32_t ldm0 = smb + SM_B + klrow * 64 + (uint32_t)(((0 + (sel >> 1)) ^ swl) * 16);
    const uint32_t ldm1 = smb + SM_B + klrow * 64 + (uint32_t)(((2 + (sel >> 1)) ^ swl) * 16);

    const uint32_t mbc0 = khalf ? mb10 : mb00;   // my khalf, kst 0-3
    const uint32_t mbc1 = khalf ? mb11 : mb01;   // my khalf, kst 4-7

    for (int t = 0; t < T; ++t) {
        const int par = t & 1;

        // ---- stage s limbs: single slice-ready spin, 8 chunked bulk copies ----
        if (tid == 0) {
            acq_spin(&g_sready[ks], 16u * (unsigned)(t + 1));
            mbar_arrive_tx(mb00, 8192); mbar_arrive_tx(mb01, 8192);
            mbar_arrive_tx(mb10, 8192); mbar_arrive_tx(mb11, 8192);
            // chunk-0 (kst 0-3) of both khalves first, then chunk-1
#pragma unroll
            for (int c = 0; c < 2; ++c)
#pragma unroll
                for (int kh = 0; kh < 2; ++kh) {
                    uint32_t mb = (kh ? (c ? mb11 : mb10) : (c ? mb01 : mb00));
#pragma unroll
                    for (int l = 0; l < 2; ++l)
                        bulk_cp(smb + SM_B + l * BTILE + kh * 8192 + c * 4096,
                                &g_sT[par][l][ks * KSLICE + kh * 128 + c * 64][0],
                                4096, mb);
                }
        }

        const float xv = __ldg(&x_in[(size_t)t * (TT_B * TT_N) + b * TT_N + jg]);

        // ---- GEMM: 3 fp16 limb products (Wh*Sh + Wh*Sm + Wm*Sh) ----
        float d[4][4];
#pragma unroll
        for (int n = 0; n < 4; ++n)
#pragma unroll
            for (int q = 0; q < 4; ++q) d[n][q] = 0.f;

        mbar_wait(mbc0, (uint32_t)(t & 1));
#pragma unroll
        for (int kst = 0; kst < 8; ++kst) {
            if (kst == 4) mbar_wait(mbc1, (uint32_t)(t & 1));
            const uint32_t off = (uint32_t)kst * 1024;
            uint32_t bh[8], bm[8];
            ldmT(bh + 0, ldm0 + 0 * BTILE + off);
            ldmT(bh + 4, ldm1 + 0 * BTILE + off);
            ldmT(bm + 0, ldm0 + 1 * BTILE + off);
            ldmT(bm + 4, ldm1 + 1 * BTILE + off);
#pragma unroll
            for (int n = 0; n < 4; ++n) {
                const int i0 = n * 2;
                mma_f16(d[n], a_h[kst], bh[i0], bh[i0 + 1]);   // Wh*Sh
                mma_f16(d[n], a_h[kst], bm[i0], bm[i0 + 1]);   // Wh*Sm
                mma_f16(d[n], a_m[kst], bh[i0], bh[i0 + 1]);   // Wm*Sh
            }
        }

        // ---- khalf pair-reduce -> SMEM pt tile -> coalesced STG.128 ----
        {
            char* rbase = smem + SM_RED + mt * (16 * REDP);
            float* pt = (float*)(smem + SM_PT);
            if (khalf == 1) {
#pragma unroll
                for (int n = 0; n < 4; ++n) {
                    char* p0 = rbase + g * REDP + (n * 8 + 2 * tg) * 4;
                    char* p1 = rbase + (g + 8) * REDP + (n * 8 + 2 * tg) * 4;
                    *(float2*)p0 = make_float2(d[n][0], d[n][1]);
                    *(float2*)p1 = make_float2(d[n][2], d[n][3]);
                }
            }
            __syncthreads();
            if (khalf == 0) {
#pragma unroll
                for (int n = 0; n < 4; ++n) {
                    const char* p0 = rbase + g * REDP + (n * 8 + 2 * tg) * 4;
                    const char* p1 = rbase + (g + 8) * REDP + (n * 8 + 2 * tg) * 4;
                    float2 r0 = *(const float2*)p0;
                    float2 r1 = *(const float2*)p1;
#pragma unroll
                    for (int q = 0; q < 4; ++q) {
                        float val = d[n][q] + ((q == 0) ? r0.x : (q == 1) ? r0.y
                                            : (q == 2) ? r1.x : r1.y);
                        int bb = n * 8 + 2 * tg + (q & 1);
                        int jj = mt * 16 + g + ((q >> 1) * 8);
                        pt[bb * PTPITCH + jj] = val;    // bank-clean (pitch 132)
                    }
                }
            }
            __syncthreads();
            // coalesced copy-out: thread -> (b, 32B chunk); parity-doubled dst
            {
                const float4* srcp =
                    (const float4*)(smem + SM_PT + b * (PTPITCH * 4)) + m16 * 2;
                float4* dstp = (float4*)(&g_part[par][blockIdx.x][b][0]) + m16 * 2;
                dstp[0] = srcp[0];
                dstp[1] = srcp[1];
            }
        }

        // ---- row-scoped partials sync: per-warp acquire gate ----
        __syncthreads();                 // all partial STGs issued by CTA
        if (tid == 0) rel_add(&g_pready[cg]);
        if (lane == 0) acq_spin(&g_pready[cg], 8u * (unsigned)(t + 1));
        __syncwarp();                    // warp-local: lanes gated by lane0's acquire

        // ---- K-split reduce (L2) + LIF dynamics ----
        float I = 0.f;
        {
            const int jl = ks * 16 + m16;
#pragma unroll
            for (int kk = 0; kk < KS_N; ++kk)
                I += __ldcg(&g_part[par][cg * 8 + kk][b][jl]);
        }
        I += 1.75f * xv;

        float dv     = (eL - v + I * nR) / tm;
        float v_next = v + dv;
        float gating = fminf(fmaxf(v_next / 30.0f, 0.0f), 1.0f);
        float cdv    = fminf(fmaxf(dv / dvmax, 0.0f), 1.0f);
        s = s + (-s + gating * cdv) / tsv;
        v = (v_next >= 30.0f) ? eL : v_next;

        if (t + 1 < T) {
            // ---- publish s limbs FIRST (critical path) ----
            uint16_t h, m; split2(s, h, m);
            char* bb_ = smem + SM_BOUNCE;
            *(uint16_t*)(bb_ + (m16 * 2 + 0) * 64 + co) = h;
            *(uint16_t*)(bb_ + (m16 * 2 + 1) * 64 + co) = m;
            __syncthreads();
            if (tid < 128) {
                const int ll = tid >> 6;           // limb
                const int rr = tid & 63;
                const int jl = rr >> 2;            // 0..15
                const int c  = rr & 3;
                const char* src = bb_ + (jl * 2 + ll) * 64 + c * 16;
                char* dst = (char*)&g_sT[par ^ 1][ll][j0 + jl][0] + c * 16;
                *(uint4*)dst = *(const uint4*)src;
            }
            __syncthreads();             // copy-out STGs issued by all
            if (tid == 0) rel_add(&g_sready[cg >> 1]);   // slice ready for t+1
        }

        // ---- deferred output epilogue (overlaps next step's TMA wait) ----
        out[(size_t)t * (TT_B * TT_N) + b * TT_N + jg] =
            1.0f / (1.0f + __expf(30.0f - v_next));
    }
}

extern "C" void kernel_launch(void* const* d_in, const int* in_sizes, int n_in,
                              void* d_out, int out_size) {
    const float* x_in  = (const float*)d_in[0];
    const float* v0    = (const float*)d_in[1];
    const float* s0    = (const float*)d_in[2];
    const float* w     = (const float*)d_in[3];
    const float* E_L   = (const float*)d_in[4];
    const float* tau_m = (const float*)d_in[5];
    const float* tau_s = (const float*)d_in[6];
    const int*   ntype = (const int*)d_in[7];
    float* out = (float*)d_out;

    const int T = in_sizes[0] / (TT_B * TT_N);

    cudaFuncSetAttribute(lif_kernel,
                         cudaFuncAttributeMaxDynamicSharedMemorySize, SM_TOTAL);

    lif_init_kernel<<<1, 1>>>();
    lif_kernel<<<NCTA, TPB, SM_TOTAL>>>(x_in, v0, s0, w, E_L, tau_m, tau_s,
                                        ntype, out, T);
}

// round 15
// speedup vs baseline: 1.3711x; 1.3711x over previous
#include <cuda_runtime.h>
#include <cuda_fp16.h>
#include <cstdint>
#include <math.h>

// ---------------- configuration ----------------
#define TT_B   32
#define TT_N   2048
#define NCTA   128          // 16 colgroups x 8 K-splits (single wave)
#define TPB    512          // 16 warps = 8 mtiles x 2 khalves
#define KS_N   8
#define KSLICE 256          // K per CTA
#define MTILE  128          // j per CTA

// SMEM layout
#define SM_B      0                        // 2 limb tiles [256 k][64B], swizzled
#define BTILE     16384
#define SM_RED    (2 * BTILE)              // 32768 ; 8 mtiles x 16j x 160B
#define REDP      160
#define SM_PT     (SM_RED + 8 * 16 * REDP) // 53248 ; partial tile 32 x 528B
#define PTPITCH   132                      // floats per b-row (528B, bank-clean)
#define SM_BOUNCE (SM_PT + TT_B * PTPITCH * 4)   // 70144 ; 32 rows x 64B
#define SM_MBAR   (SM_BOUNCE + 2048)       // 72192 ; four mbars
#define SM_TOTAL  (SM_MBAR + 64)

// ---------------- device globals ----------------
// s limbs TRANSPOSED: [parity][limb][k(neuron)][b] fp16, 64B rows, chunk-swizzled
__device__ __align__(128) __half g_sT[2][2][TT_N][TT_B];
__device__ __align__(128) float g_part[2][NCTA][TT_B][MTILE]; // [par][cta][b][j]
__device__ unsigned g_sready[8];    // per s-slice publish counters (+16/step)
__device__ unsigned g_pready[16];   // per cg-row partial counters (+8/step)

__global__ void lif_init_kernel() {
    for (int i = 0; i < 8; ++i) g_sready[i] = 0u;
    for (int i = 0; i < 16; ++i) g_pready[i] = 0u;
}

// ---------------- helpers ----------------
__device__ __forceinline__ void mma_f16(float* d, const uint32_t* a,
                                        uint32_t b0, uint32_t b1) {
    asm volatile("mma.sync.aligned.m16n8k16.row.col.f32.f16.f16.f32 "
                 "{%0,%1,%2,%3}, {%4,%5,%6,%7}, {%8,%9}, {%0,%1,%2,%3};"
                 : "+f"(d[0]), "+f"(d[1]), "+f"(d[2]), "+f"(d[3])
                 : "r"(a[0]), "r"(a[1]), "r"(a[2]), "r"(a[3]),
                   "r"(b0), "r"(b1));
}
__device__ __forceinline__ void ldmT(uint32_t* r, uint32_t addr) {
    asm volatile("ldmatrix.sync.aligned.m8n8.x4.trans.shared.b16 {%0,%1,%2,%3}, [%4];"
                 : "=r"(r[0]), "=r"(r[1]), "=r"(r[2]), "=r"(r[3]) : "r"(addr));
}
__device__ __forceinline__ uint32_t smem_u32(const void* p) {
    uint32_t a;
    asm("{ .reg .u64 t; cvta.to.shared.u64 t, %1; cvt.u32.u64 %0, t; }" : "=r"(a) : "l"(p));
    return a;
}
__device__ __forceinline__ void mbar_init(uint32_t mbar, uint32_t cnt) {
    asm volatile("mbarrier.init.shared.b64 [%0], %1;" :: "r"(mbar), "r"(cnt) : "memory");
}
__device__ __forceinline__ void mbar_arrive_tx(uint32_t mbar, uint32_t bytes) {
    asm volatile("mbarrier.arrive.expect_tx.shared.b64 _, [%0], %1;"
                 :: "r"(mbar), "r"(bytes) : "memory");
}
__device__ __forceinline__ void mbar_wait(uint32_t mbar, uint32_t parity) {
    asm volatile("{\n\t.reg .pred P1;\n\tWL%=:\n\t"
                 "mbarrier.try_wait.parity.acquire.cta.shared::cta.b64 P1, [%0], %1, 0x989680;\n\t"
                 "@P1 bra.uni WD%=;\n\tbra.uni WL%=;\n\tWD%=:\n\t}"
                 :: "r"(mbar), "r"(parity) : "memory");
}
__device__ __forceinline__ void bulk_cp(uint32_t dst, const void* src,
                                        uint32_t bytes, uint32_t mbar) {
    asm volatile("cp.async.bulk.shared::cluster.global.mbarrier::complete_tx::bytes "
                 "[%0], [%1], %2, [%3];"
                 :: "r"(dst), "l"(src), "r"(bytes), "r"(mbar) : "memory");
}
__device__ __forceinline__ void rel_add(unsigned* p) {
    asm volatile("red.release.gpu.global.add.u32 [%0], %1;"
                 :: "l"(p), "r"(1u) : "memory");
}
__device__ __forceinline__ void acq_spin(unsigned* p, unsigned tgt) {
    unsigned vv;
    do {
        asm volatile("ld.acquire.gpu.global.u32 %0, [%1];"
                     : "=r"(vv) : "l"(p) : "memory");
    } while (vv < tgt);
}
// exact 2-way fp16 split: x = h + m + eps, |eps| <= 2^-22 |x|
__device__ __forceinline__ void split2(float x, uint16_t& h, uint16_t& m) {
    __half hh = __float2half_rn(x);
    float r = x - __half2float(hh);
    __half mm = __float2half_rn(r);
    h = __half_as_ushort(hh); m = __half_as_ushort(mm);
}

__global__ void __launch_bounds__(TPB, 1)
lif_kernel(const float* __restrict__ x_in, const float* __restrict__ v0,
           const float* __restrict__ s0,   const float* __restrict__ w,
           const float* __restrict__ E_Lp, const float* __restrict__ tau_mp,
           const float* __restrict__ tau_sp, const int* __restrict__ ntype,
           float* __restrict__ out, int T)
{
    extern __shared__ char smem[];
    const uint32_t smb = smem_u32(smem);
    // mbar[khalf][chunk] : chunk = kst quarter-pair (kst 0-3 / 4-7)
    const uint32_t mb00 = smb + SM_MBAR;
    const uint32_t mb01 = smb + SM_MBAR + 8;
    const uint32_t mb10 = smb + SM_MBAR + 16;
    const uint32_t mb11 = smb + SM_MBAR + 24;

    const int tid   = threadIdx.x;
    const int lane  = tid & 31;
    const int wid   = tid >> 5;
    const int g     = lane >> 2;
    const int tg    = lane & 3;
    const int cg    = blockIdx.x >> 3;
    const int ks    = blockIdx.x & 7;
    const int khalf = wid & 1;
    const int mt    = wid >> 1;

    const int jbase = cg * MTILE + mt * 16;
    const int kbase = ks * KSLICE + khalf * 128;

    if (tid == 0) {
        mbar_init(mb00, 1); mbar_init(mb01, 1);
        mbar_init(mb10, 1); mbar_init(mb11, 1);
    }

    // ---- one-time A build: Weff[k][j] = w[k][j]*nt[k], diag 0; fp16 2-limb ----
    auto weff = [&](int k, int j) -> float {
        if (k == j) return 0.f;
        return w[(size_t)k * TT_N + j] * (float)__ldg(&ntype[k]);
    };
    uint32_t a_h[8][4], a_m[8][4];
#pragma unroll
    for (int kst = 0; kst < 8; ++kst) {
        const int rows[2] = { g, g + 8 };
        const int kk0[2]  = { kst * 16 + 2 * tg, kst * 16 + 2 * tg + 8 };
#pragma unroll
        for (int q = 0; q < 4; ++q) {
            int j = jbase + rows[q & 1];
            int k = kbase + kk0[q >> 1];
            uint16_t h0, m0, h1, m1;
            split2(weff(k,     j), h0, m0);
            split2(weff(k + 1, j), h1, m1);
            a_h[kst][q] = (uint32_t)h0 | ((uint32_t)h1 << 16);
            a_m[kst][q] = (uint32_t)m0 | ((uint32_t)m1 << 16);
        }
    }

    // ---- dynamics ownership: tid = b*16 + m16 ----
    const int b   = tid >> 4;
    const int m16 = tid & 15;
    const int j0  = cg * MTILE + ks * 16;
    const int jg  = j0 + m16;
    float v = v0[b * TT_N + jg];
    float s = s0[b * TT_N + jg];
    const float eL    = E_Lp[jg];
    const float tm    = tau_mp[jg];
    const float tsv   = tau_sp[jg];
    const float nR    = (30.0f - eL) * 1.1f;
    const float dvmax = 30.0f - eL;

    // swizzled byte offset of (b) within the 64B k-row of jg
    const int co = (((b >> 3) ^ ((jg >> 1) & 3)) * 16) + ((b & 7) * 2);

    {   // publish initial s limbs (parity 0), direct swizzled stores
        uint16_t h, m; split2(s, h, m);
        *(uint16_t*)((char*)&g_sT[0][0][jg][0] + co) = h;
        *(uint16_t*)((char*)&g_sT[0][1][jg][0] + co) = m;
    }
    __syncthreads();
    if (tid == 0) rel_add(&g_sready[cg >> 1]);   // initial publish -> t=0 ready

    // ldmatrix lane address bases (R6-validated swizzle)
    const int r8  = lane & 7;
    const int sel = lane >> 3;
    const int swl = (r8 >> 1) & 3;
    const int klrow = khalf * 128 + (sel & 1) * 8 + r8;
    const uint32_t ldm0 = smb + SM_B + klrow * 64 + (uint32_t)(((0 + (sel >> 1)) ^ swl) * 16);
    const uint32_t ldm1 = smb + SM_B + klrow * 64 + (uint32_t)(((2 + (sel >> 1)) ^ swl) * 16);

    const uint32_t mbc0 = khalf ? mb10 : mb00;   // my khalf, kst 0-3
    const uint32_t mbc1 = khalf ? mb11 : mb01;   // my khalf, kst 4-7

    for (int t = 0; t < T; ++t) {
        const int par = t & 1;

        // ---- stage s limbs: single slice-ready spin, 8 chunked bulk copies ----
        if (tid == 0) {
            acq_spin(&g_sready[ks], 16u * (unsigned)(t + 1));
            mbar_arrive_tx(mb00, 8192); mbar_arrive_tx(mb01, 8192);
            mbar_arrive_tx(mb10, 8192); mbar_arrive_tx(mb11, 8192);
            // chunk-0 (kst 0-3) of both khalves first, then chunk-1
#pragma unroll
            for (int c = 0; c < 2; ++c)
#pragma unroll
                for (int kh = 0; kh < 2; ++kh) {
                    uint32_t mb = (kh ? (c ? mb11 : mb10) : (c ? mb01 : mb00));
#pragma unroll
                    for (int l = 0; l < 2; ++l)
                        bulk_cp(smb + SM_B + l * BTILE + kh * 8192 + c * 4096,
                                &g_sT[par][l][ks * KSLICE + kh * 128 + c * 64][0],
                                4096, mb);
                }
        }

        const float xv = __ldg(&x_in[(size_t)t * (TT_B * TT_N) + b * TT_N + jg]);

        // ---- GEMM: 3 fp16 limb products (Wh*Sh + Wh*Sm + Wm*Sh) ----
        float d[4][4];
#pragma unroll
        for (int n = 0; n < 4; ++n)
#pragma unroll
            for (int q = 0; q < 4; ++q) d[n][q] = 0.f;

        mbar_wait(mbc0, (uint32_t)(t & 1));
#pragma unroll
        for (int kst = 0; kst < 8; ++kst) {
            if (kst == 4) mbar_wait(mbc1, (uint32_t)(t & 1));
            const uint32_t off = (uint32_t)kst * 1024;
            uint32_t bh[8], bm[8];
            ldmT(bh + 0, ldm0 + 0 * BTILE + off);
            ldmT(bh + 4, ldm1 + 0 * BTILE + off);
            ldmT(bm + 0, ldm0 + 1 * BTILE + off);
            ldmT(bm + 4, ldm1 + 1 * BTILE + off);
#pragma unroll
            for (int n = 0; n < 4; ++n) {
                const int i0 = n * 2;
                mma_f16(d[n], a_h[kst], bh[i0], bh[i0 + 1]);   // Wh*Sh
                mma_f16(d[n], a_h[kst], bm[i0], bm[i0 + 1]);   // Wh*Sm
                mma_f16(d[n], a_m[kst], bh[i0], bh[i0 + 1]);   // Wm*Sh
            }
        }

        // ---- khalf pair-reduce -> SMEM pt tile -> coalesced STG.128 ----
        {
            char* rbase = smem + SM_RED + mt * (16 * REDP);
            float* pt = (float*)(smem + SM_PT);
            if (khalf == 1) {
#pragma unroll
                for (int n = 0; n < 4; ++n) {
                    char* p0 = rbase + g * REDP + (n * 8 + 2 * tg) * 4;
                    char* p1 = rbase + (g + 8) * REDP + (n * 8 + 2 * tg) * 4;
                    *(float2*)p0 = make_float2(d[n][0], d[n][1]);
                    *(float2*)p1 = make_float2(d[n][2], d[n][3]);
                }
            }
            __syncthreads();
            if (khalf == 0) {
#pragma unroll
                for (int n = 0; n < 4; ++n) {
                    const char* p0 = rbase + g * REDP + (n * 8 + 2 * tg) * 4;
                    const char* p1 = rbase + (g + 8) * REDP + (n * 8 + 2 * tg) * 4;
                    float2 r0 = *(const float2*)p0;
                    float2 r1 = *(const float2*)p1;
#pragma unroll
                    for (int q = 0; q < 4; ++q) {
                        float val = d[n][q] + ((q == 0) ? r0.x : (q == 1) ? r0.y
                                            : (q == 2) ? r1.x : r1.y);
                        int bb = n * 8 + 2 * tg + (q & 1);
                        int jj = mt * 16 + g + ((q >> 1) * 8);
                        pt[bb * PTPITCH + jj] = val;    // bank-clean (pitch 132)
                    }
                }
            }
            __syncthreads();
            // coalesced copy-out: thread -> (b, 32B chunk); parity-doubled dst
            {
                const float4* srcp =
                    (const float4*)(smem + SM_PT + b * (PTPITCH * 4)) + m16 * 2;
                float4* dstp = (float4*)(&g_part[par][blockIdx.x][b][0]) + m16 * 2;
                dstp[0] = srcp[0];
                dstp[1] = srcp[1];
            }
        }

        // ---- row-scoped partials sync: 8 producers per cg row (R12 shape) ----
        __syncthreads();                 // all partial STGs issued by CTA
        if (tid == 0) {
            rel_add(&g_pready[cg]);
            acq_spin(&g_pready[cg], 8u * (unsigned)(t + 1));
        }
        __syncthreads();                 // row partials visible to all threads

        // ---- K-split reduce (L2) + LIF dynamics ----
        float I = 0.f;
        {
            const int jl = ks * 16 + m16;
#pragma unroll
            for (int kk = 0; kk < KS_N; ++kk)
                I += __ldcg(&g_part[par][cg * 8 + kk][b][jl]);
        }
        I += 1.75f * xv;

        float dv     = (eL - v + I * nR) / tm;
        float v_next = v + dv;
        float gating = fminf(fmaxf(v_next / 30.0f, 0.0f), 1.0f);
        float cdv    = fminf(fmaxf(dv / dvmax, 0.0f), 1.0f);
        s = s + (-s + gating * cdv) / tsv;
        v = (v_next >= 30.0f) ? eL : v_next;

        if (t + 1 < T) {
            // ---- publish s limbs FIRST (loop-carried critical path) ----
            uint16_t h, m; split2(s, h, m);
            char* bb_ = smem + SM_BOUNCE;
            *(uint16_t*)(bb_ + (m16 * 2 + 0) * 64 + co) = h;
            *(uint16_t*)(bb_ + (m16 * 2 + 1) * 64 + co) = m;
            __syncthreads();
            if (tid < 128) {
                const int ll = tid >> 6;           // limb
                const int rr = tid & 63;
                const int jl = rr >> 2;            // 0..15
                const int c  = rr & 3;
                const char* src = bb_ + (jl * 2 + ll) * 64 + c * 16;
                char* dst = (char*)&g_sT[par ^ 1][ll][j0 + jl][0] + c * 16;
                *(uint4*)dst = *(const uint4*)src;
            }
            __syncthreads();             // copy-out STGs issued by all
            if (tid == 0) rel_add(&g_sready[cg >> 1]);   // slice ready for t+1
        }

        // ---- deferred output epilogue (overlaps next step's TMA wait) ----
        out[(size_t)t * (TT_B * TT_N) + b * TT_N + jg] =
            1.0f / (1.0f + __expf(30.0f - v_next));
    }
}

extern "C" void kernel_launch(void* const* d_in, const int* in_sizes, int n_in,
                              void* d_out, int out_size) {
    const float* x_in  = (const float*)d_in[0];
    const float* v0    = (const float*)d_in[1];
    const float* s0    = (const float*)d_in[2];
    const float* w     = (const float*)d_in[3];
    const float* E_L   = (const float*)d_in[4];
    const float* tau_m = (const float*)d_in[5];
    const float* tau_s = (const float*)d_in[6];
    const int*   ntype = (const int*)d_in[7];
    float* out = (float*)d_out;

    const int T = in_sizes[0] / (TT_B * TT_N);

    cudaFuncSetAttribute(lif_kernel,
                         cudaFuncAttributeMaxDynamicSharedMemorySize, SM_TOTAL);

    lif_init_kernel<<<1, 1>>>();
    lif_kernel<<<NCTA, TPB, SM_TOTAL>>>(x_in, v0, s0, w, E_L, tau_m, tau_s,
                                        ntype, out, T);
}